// round 10
// baseline (speedup 1.0000x reference)
#include <cuda_runtime.h>
#include <cuda_bf16.h>
#include <cstdint>

#define DIN   128
#define DOUT  128
#define MTILE 128
#define KC    64
#define NCHUNK 4
#define MAXN  50000
#define MAXE  800000

#define TBS   16384                 // swizzled bf16 tile: 128 rows x 128B
#define SM_B  0                     // 8 tiles (4 chunks x hi/lo)
#define SM_AH (8*TBS)               // 131072
#define SM_AL (9*TBS)               // 147456
#define SM_ST (10*TBS)              // 163840: fp32 A staging, 2 x 32KB
#define STG_B 32768
#define SMEM_TOTAL (10*TBS + 2*STG_B)   // 229376 (<= 232448)

#define SCANB 256
#define NBLK ((MAXN + SCANB - 1) / SCANB)

__device__ float g_agg[MAXN * DIN];
__device__ int   g_count[MAXN];
__device__ int   g_off[MAXN + 1];
__device__ int   g_cursor[MAXN];
__device__ int   g_srcs[MAXE];
__device__ int   g_bsum[NBLK];
__device__ int   g_boff[NBLK];
__device__ __nv_bfloat16 g_Bh[NCHUNK * 128 * KC];
__device__ __nv_bfloat16 g_Bl[NCHUNK * 128 * KC];
__device__ int   g_is64;

// ---------------------------------------------------------------- helpers
__device__ __forceinline__ uint32_t smem_u32(const void* p) {
    uint32_t a;
    asm("{ .reg .u64 t; cvta.to.shared.u64 t, %1; cvt.u32.u64 %0, t; }" : "=r"(a) : "l"(p));
    return a;
}
#define LDMX4(r0, r1, r2, r3, a) \
    asm volatile("ldmatrix.sync.aligned.m8n8.x4.shared.b16 {%0,%1,%2,%3}, [%4];" \
                 : "=r"(r0), "=r"(r1), "=r"(r2), "=r"(r3) : "r"(a))
#define MMA(c, a0, a1, a2, a3, b0, b1) \
    asm volatile("mma.sync.aligned.m16n8k16.row.col.f32.bf16.bf16.f32 " \
                 "{%0,%1,%2,%3}, {%4,%5,%6,%7}, {%8,%9}, {%0,%1,%2,%3};" \
                 : "+f"((c)[0]), "+f"((c)[1]), "+f"((c)[2]), "+f"((c)[3]) \
                 : "r"(a0), "r"(a1), "r"(a2), "r"(a3), "r"(b0), "r"(b1))
#define CPA16(dst, src) \
    asm volatile("cp.async.cg.shared.global [%0], [%1], 16;" :: "r"(dst), "l"(src))
#define CPA16P(dst, src, sz) \
    asm volatile("cp.async.cg.shared.global [%0], [%1], 16, %2;" :: "r"(dst), "l"(src), "r"(sz))

__device__ __forceinline__ void split4(float4 v, uint2& hi, uint2& lo) {
    __nv_bfloat16 hx = __float2bfloat16(v.x), hy = __float2bfloat16(v.y);
    __nv_bfloat16 hz = __float2bfloat16(v.z), hw = __float2bfloat16(v.w);
    __nv_bfloat16 lx = __float2bfloat16(v.x - __bfloat162float(hx));
    __nv_bfloat16 ly = __float2bfloat16(v.y - __bfloat162float(hy));
    __nv_bfloat16 lz = __float2bfloat16(v.z - __bfloat162float(hz));
    __nv_bfloat16 lw = __float2bfloat16(v.w - __bfloat162float(hw));
    hi.x = ((uint32_t)__bfloat16_as_ushort(hy) << 16) | __bfloat16_as_ushort(hx);
    hi.y = ((uint32_t)__bfloat16_as_ushort(hw) << 16) | __bfloat16_as_ushort(hz);
    lo.x = ((uint32_t)__bfloat16_as_ushort(ly) << 16) | __bfloat16_as_ushort(lx);
    lo.y = ((uint32_t)__bfloat16_as_ushort(lw) << 16) | __bfloat16_as_ushort(lz);
}

// ---------------------------------------------------------------- CSR build
__global__ void zero_count_kernel(int N) {
    int i = blockIdx.x * blockDim.x + threadIdx.x;
    if (i == 0) g_is64 = 1;
    if (i < N) g_count[i] = 0;
}
__global__ void detect_kernel(const long long* __restrict__ ei, int nwords, int N) {
    int i = threadIdx.x + blockIdx.x * blockDim.x;
    if (i < nwords && (unsigned long long)ei[i] >= (unsigned long long)N)
        atomicAnd(&g_is64, 0);
}
// 4 edges/thread, vectorized loads (MLP)
__global__ void hist_kernel(const void* __restrict__ ei_raw, int E, int N) {
    int e0 = (blockIdx.x * blockDim.x + threadIdx.x) * 4;
    if (e0 >= E) return;
    int cnt = E - e0; if (cnt > 4) cnt = 4;
    int d[4];
    if (g_is64) {
        const long long* ei = (const long long*)ei_raw + E + e0;
        if (cnt == 4) {
            longlong2 a = *(const longlong2*)ei;
            longlong2 b = *(const longlong2*)(ei + 2);
            d[0] = (int)a.x; d[1] = (int)a.y; d[2] = (int)b.x; d[3] = (int)b.y;
        } else for (int i = 0; i < cnt; i++) d[i] = (int)ei[i];
    } else {
        const int* ei = (const int*)ei_raw + E + e0;
        if (cnt == 4) {
            int4 a = *(const int4*)ei;
            d[0] = a.x; d[1] = a.y; d[2] = a.z; d[3] = a.w;
        } else for (int i = 0; i < cnt; i++) d[i] = ei[i];
    }
    #pragma unroll
    for (int i = 0; i < 4; i++)
        if (i < cnt && (unsigned)d[i] < (unsigned)N) atomicAdd(&g_count[d[i]], 1);
}
__global__ void scan1_kernel(int N) {
    __shared__ int s[SCANB];
    int i = blockIdx.x * SCANB + threadIdx.x;
    int v = (i < N) ? g_count[i] : 0;
    s[threadIdx.x] = v;
    __syncthreads();
    for (int off = 1; off < SCANB; off <<= 1) {
        int u = (threadIdx.x >= off) ? s[threadIdx.x - off] : 0;
        __syncthreads(); s[threadIdx.x] += u; __syncthreads();
    }
    if (threadIdx.x == SCANB - 1) g_bsum[blockIdx.x] = s[SCANB - 1];
}
__global__ void scan2_kernel(int nblk, int N) {
    __shared__ int s[SCANB];
    int t = threadIdx.x;
    int v = (t < nblk) ? g_bsum[t] : 0;
    s[t] = v; __syncthreads();
    for (int off = 1; off < SCANB; off <<= 1) {
        int u = (t >= off) ? s[t - off] : 0;
        __syncthreads(); s[t] += u; __syncthreads();
    }
    if (t < nblk) g_boff[t] = s[t] - v;
    if (t == SCANB - 1) g_off[N] = s[SCANB - 1];
}
__global__ void scan3_kernel(int N) {
    __shared__ int s[SCANB];
    int i = blockIdx.x * SCANB + threadIdx.x;
    int v = (i < N) ? g_count[i] : 0;
    s[threadIdx.x] = v; __syncthreads();
    for (int off = 1; off < SCANB; off <<= 1) {
        int u = (threadIdx.x >= off) ? s[threadIdx.x - off] : 0;
        __syncthreads(); s[threadIdx.x] += u; __syncthreads();
    }
    if (i < N) {
        int excl = g_boff[blockIdx.x] + s[threadIdx.x] - v;
        g_off[i] = excl;
        g_cursor[i] = excl;
    }
}
// 2 edges/thread, vectorized
__global__ void scatter_kernel(const void* __restrict__ ei_raw, int E, int N) {
    int e0 = (blockIdx.x * blockDim.x + threadIdx.x) * 2;
    if (e0 >= E) return;
    int cnt = E - e0; if (cnt > 2) cnt = 2;
    int s[2], d[2];
    if (g_is64) {
        const long long* ei = (const long long*)ei_raw;
        if (cnt == 2) {
            longlong2 sv = *(const longlong2*)(ei + e0);
            longlong2 dv = *(const longlong2*)(ei + E + e0);
            s[0] = (int)sv.x; s[1] = (int)sv.y; d[0] = (int)dv.x; d[1] = (int)dv.y;
        } else { s[0] = (int)ei[e0]; d[0] = (int)ei[E + e0]; }
    } else {
        const int* ei = (const int*)ei_raw;
        if (cnt == 2) {
            int2 sv = *(const int2*)(ei + e0);
            int2 dv = *(const int2*)(ei + E + e0);
            s[0] = sv.x; s[1] = sv.y; d[0] = dv.x; d[1] = dv.y;
        } else { s[0] = ei[e0]; d[0] = ei[E + e0]; }
    }
    #pragma unroll
    for (int i = 0; i < 2; i++)
        if (i < cnt && (unsigned)s[i] < (unsigned)N && (unsigned)d[i] < (unsigned)N) {
            int pos = atomicAdd(&g_cursor[d[i]], 1);
            g_srcs[pos] = s[i];
        }
}
// one warp per node, MLP=4
__global__ void gather_kernel(const float4* __restrict__ x, int N) {
    int w = (blockIdx.x * blockDim.x + threadIdx.x) >> 5;
    int lane = threadIdx.x & 31;
    if (w >= N) return;
    int beg = g_off[w], end = g_off[w + 1];
    float4 acc = make_float4(0.f, 0.f, 0.f, 0.f);
    for (int j = beg; j < end; j += 32) {
        int cnt = end - j; if (cnt > 32) cnt = 32;
        int s = (lane < cnt) ? g_srcs[j + lane] : 0;
        int i = 0;
        for (; i + 4 <= cnt; i += 4) {
            int s0 = __shfl_sync(0xffffffffu, s, i);
            int s1 = __shfl_sync(0xffffffffu, s, i + 1);
            int s2 = __shfl_sync(0xffffffffu, s, i + 2);
            int s3 = __shfl_sync(0xffffffffu, s, i + 3);
            float4 v0 = x[(size_t)s0 * 32 + lane];
            float4 v1 = x[(size_t)s1 * 32 + lane];
            float4 v2 = x[(size_t)s2 * 32 + lane];
            float4 v3 = x[(size_t)s3 * 32 + lane];
            acc.x += v0.x + v1.x + v2.x + v3.x;
            acc.y += v0.y + v1.y + v2.y + v3.y;
            acc.z += v0.z + v1.z + v2.z + v3.z;
            acc.w += v0.w + v1.w + v2.w + v3.w;
        }
        for (; i < cnt; i++) {
            int si = __shfl_sync(0xffffffffu, s, i);
            float4 v = x[(size_t)si * 32 + lane];
            acc.x += v.x; acc.y += v.y; acc.z += v.z; acc.w += v.w;
        }
    }
    ((float4*)g_agg)[(size_t)w * 32 + lane] = acc;
}

// ---------------------------------------------------------------- W pre-split
__global__ void wprep_kernel(const float* __restrict__ W_rel,
                             const float* __restrict__ W_root) {
    int q = blockIdx.x * blockDim.x + threadIdx.x;
    if (q >= DOUT * 256 / 4) return;
    int row = q >> 6;
    int k = (q & 63) * 4;
    int c = k >> 6, kk = k & 63;
    const float* src = (c < 2) ? &W_rel[row * DIN + c * KC + kk]
                               : &W_root[row * DIN + (c - 2) * KC + kk];
    float4 v = *(const float4*)src;
    uint2 h, l; split4(v, h, l);
    int didx = (c * 128 + row) * KC + kk;
    *(uint2*)((char*)g_Bh + didx * 2) = h;
    *(uint2*)((char*)g_Bl + didx * 2) = l;
}

// ---------------------------------------------------------------- HMMA GEMM
// XOR-swizzled tiles: byte(row, seg) = row*128 + ((seg ^ (row&7))<<4)
__global__ __launch_bounds__(256, 1)
void gemm_hmma_kernel(const float* __restrict__ x,
                      const float* __restrict__ bias,
                      float* __restrict__ out, int N) {
    extern __shared__ char smem[];
    uint32_t base = smem_u32(smem);
    int tid = threadIdx.x, wid = tid >> 5, lane = tid & 31;
    int wm = wid & 3, wn = wid >> 2;
    int node0 = blockIdx.x * MTILE;

    // ---- B: all 4 chunks hi/lo, cp.async, swizzled dst
    #pragma unroll
    for (int i = 0; i < 32; i++) {
        int o = tid + i * 256;                  // 8192 x 16B segments
        int c = o >> 11;
        int hl = (o >> 10) & 1;
        int row = (o >> 3) & 127;
        int seg = o & 7;
        const __nv_bfloat16* g = (hl ? g_Bl : g_Bh) + ((c * 128 + row) * KC + seg * 8);
        uint32_t dst = base + (uint32_t)(c * 2 + hl) * TBS + row * 128 + ((seg ^ (row & 7)) << 4);
        CPA16(dst, g);
    }
    // ---- A chunk 0 staging (fp32, linear layout)
    {
        const float* asrc = g_agg + (size_t)node0 * DIN;
        #pragma unroll
        for (int i = 0; i < 8; i++) {
            int idx = tid + i * 256;
            int row = idx >> 4, c4 = idx & 15;
            uint32_t dst = base + SM_ST + row * 256 + c4 * 16;
            int sz = (node0 + row < N) ? 16 : 0;
            CPA16P(dst, asrc + (size_t)row * DIN + c4 * 4, sz);
        }
    }
    asm volatile("cp.async.commit_group;" ::: "memory");   // G0 = B + A0

    float acc[2][8][4];
    #pragma unroll
    for (int a = 0; a < 2; a++)
        #pragma unroll
        for (int b = 0; b < 8; b++)
            #pragma unroll
            for (int cc = 0; cc < 4; cc++) acc[a][b][cc] = 0.f;

    int rA0 = wm * 32 + (lane & 15);
    int segA = lane >> 4;
    int rB0 = wn * 64 + (lane & 7) + ((lane >> 4) << 3);
    int segB = (lane >> 3) & 1;
    int xr = lane & 7;                           // (row & 7) for all fragment rows

    for (int c = 0; c < NCHUNK; c++) {
        int buf = c & 1;
        // prefetch A chunk c+1 into the other staging buffer
        if (c + 1 < NCHUNK) {
            int cn = c + 1;
            const float* asrc = (cn < 2) ? g_agg + (size_t)node0 * DIN + cn * KC
                                         : x + (size_t)node0 * DIN + (cn - 2) * KC;
            #pragma unroll
            for (int i = 0; i < 8; i++) {
                int idx = tid + i * 256;
                int row = idx >> 4, c4 = idx & 15;
                uint32_t dst = base + SM_ST + (buf ^ 1) * STG_B + row * 256 + c4 * 16;
                int sz = (node0 + row < N) ? 16 : 0;
                CPA16P(dst, asrc + (size_t)row * DIN + c4 * 4, sz);
            }
            asm volatile("cp.async.commit_group;" ::: "memory");
            asm volatile("cp.async.wait_group 1;" ::: "memory");
        } else {
            asm volatile("cp.async.wait_group 0;" ::: "memory");
        }
        __syncthreads();   // staged data visible to all; prev MMA done reading sA

        // split stage[buf] -> sAh/sAl (swizzled)
        const float4* st = (const float4*)(smem + SM_ST + buf * STG_B);
        #pragma unroll
        for (int i = 0; i < 8; i++) {
            int idx = tid + i * 256;
            int row = idx >> 4, c4 = idx & 15;
            float4 v = st[row * 16 + c4];
            uint2 h, l; split4(v, h, l);
            uint32_t off = row * 128 + (((c4 >> 1) ^ (row & 7)) << 4) + (c4 & 1) * 8;
            *(uint2*)(smem + SM_AH + off) = h;
            *(uint2*)(smem + SM_AL + off) = l;
        }
        __syncthreads();

        uint32_t Bc = base + (uint32_t)(c * 2) * TBS;
        #pragma unroll
        for (int kt = 0; kt < 4; kt++) {
            uint32_t Ah[8], Al[8], Bh[16], Bl[16];
            #pragma unroll
            for (int tm = 0; tm < 2; tm++) {
                uint32_t a = base + SM_AH + (rA0 + tm * 16) * 128
                           + (((kt * 2 + segA) ^ xr) << 4);
                LDMX4(Ah[tm*4+0], Ah[tm*4+1], Ah[tm*4+2], Ah[tm*4+3], a);
                LDMX4(Al[tm*4+0], Al[tm*4+1], Al[tm*4+2], Al[tm*4+3], a + TBS);
            }
            #pragma unroll
            for (int p = 0; p < 4; p++) {
                uint32_t bb2 = Bc + (rB0 + p * 16) * 128
                             + (((kt * 2 + segB) ^ xr) << 4);
                LDMX4(Bh[p*4+0], Bh[p*4+1], Bh[p*4+2], Bh[p*4+3], bb2);
                LDMX4(Bl[p*4+0], Bl[p*4+1], Bl[p*4+2], Bl[p*4+3], bb2 + TBS);
            }
            #pragma unroll
            for (int tm = 0; tm < 2; tm++)
                #pragma unroll
                for (int tn = 0; tn < 8; tn++) {
                    int bi = (tn >> 1) * 4 + (tn & 1) * 2;
                    MMA(acc[tm][tn], Ah[tm*4+0], Ah[tm*4+1], Ah[tm*4+2], Ah[tm*4+3],
                        Bh[bi], Bh[bi+1]);
                    MMA(acc[tm][tn], Al[tm*4+0], Al[tm*4+1], Al[tm*4+2], Al[tm*4+3],
                        Bh[bi], Bh[bi+1]);
                    MMA(acc[tm][tn], Ah[tm*4+0], Ah[tm*4+1], Ah[tm*4+2], Ah[tm*4+3],
                        Bl[bi], Bl[bi+1]);
                }
        }
    }

    // ---- epilogue: bias + relu, float2 stores
    #pragma unroll
    for (int tn = 0; tn < 8; tn++) {
        int col = wn * 64 + tn * 8 + 2 * (lane & 3);
        float2 bb = *(const float2*)&bias[col];
        #pragma unroll
        for (int tm = 0; tm < 2; tm++) {
            int row = node0 + wm * 32 + tm * 16 + (lane >> 2);
            if (row < N) {
                float2 v0;
                v0.x = fmaxf(acc[tm][tn][0] + bb.x, 0.f);
                v0.y = fmaxf(acc[tm][tn][1] + bb.y, 0.f);
                *(float2*)(out + (size_t)row * DOUT + col) = v0;
            }
            if (row + 8 < N) {
                float2 v1;
                v1.x = fmaxf(acc[tm][tn][2] + bb.x, 0.f);
                v1.y = fmaxf(acc[tm][tn][3] + bb.y, 0.f);
                *(float2*)(out + (size_t)(row + 8) * DOUT + col) = v1;
            }
        }
    }
}

// ---------------------------------------------------------------- launch
extern "C" void kernel_launch(void* const* d_in, const int* in_sizes, int n_in,
                              void* d_out, int out_size) {
    const float* x      = (const float*)d_in[0];
    const void*  ei     = d_in[1];
    const float* W_rel  = (const float*)d_in[2];
    const float* b_rel  = (const float*)d_in[3];
    const float* W_root = (const float*)d_in[4];
    float* out = (float*)d_out;

    int N = in_sizes[0] / DIN;     // 50000
    int E = in_sizes[1] / 2;       // 800000
    int nblk = (N + SCANB - 1) / SCANB;

    zero_count_kernel<<<(N + 255) / 256, 256>>>(N);
    detect_kernel<<<4, 256>>>((const long long*)ei, 1024, N);
    wprep_kernel<<<(DOUT * 256 / 4 + 255) / 256, 256>>>(W_rel, W_root);
    hist_kernel<<<((E + 3) / 4 + 255) / 256, 256>>>(ei, E, N);
    scan1_kernel<<<nblk, SCANB>>>(N);
    scan2_kernel<<<1, SCANB>>>(nblk, N);
    scan3_kernel<<<nblk, SCANB>>>(N);
    scatter_kernel<<<((E + 1) / 2 + 255) / 256, 256>>>(ei, E, N);
    gather_kernel<<<(N * 32 + 255) / 256, 256>>>((const float4*)x, N);

    cudaFuncSetAttribute(gemm_hmma_kernel,
                         cudaFuncAttributeMaxDynamicSharedMemorySize, SMEM_TOTAL);
    gemm_hmma_kernel<<<(N + MTILE - 1) / MTILE, 256, SMEM_TOTAL>>>(x, b_rel, out, N);
}

// round 11
// speedup vs baseline: 1.3334x; 1.3334x over previous
#include <cuda_runtime.h>
#include <cuda_bf16.h>
#include <cstdint>

#define DIN   128
#define DOUT  128
#define MTILE 128
#define KC    64
#define NCHUNK 4
#define MAXN  50000
#define MAXE  800000
#define PITCH 72                    // bf16 per smem row (conflict-free ldmatrix)
#define T_ELEMS (128 * PITCH)
#define TB (T_ELEMS * 2)            // 18432 bytes per tile
// smem: B 4 chunks x hi/lo = 8 tiles, then A hi/lo = 2 tiles
#define SMEM_TOTAL (10 * TB)        // 184320

#define SCANB 256
#define NBLK ((MAXN + SCANB - 1) / SCANB)

__device__ float g_agg[MAXN * DIN];
__device__ int   g_count[MAXN];
__device__ int   g_off[MAXN + 1];
__device__ int   g_cursor[MAXN];
__device__ int   g_srcs[MAXE];
__device__ int   g_bsum[NBLK];
__device__ int   g_boff[NBLK];
__device__ __nv_bfloat16 g_Bh[NCHUNK * 128 * KC];
__device__ __nv_bfloat16 g_Bl[NCHUNK * 128 * KC];
__device__ int   g_is64;

// ---------------------------------------------------------------- helpers
__device__ __forceinline__ uint32_t smem_u32(const void* p) {
    uint32_t a;
    asm("{ .reg .u64 t; cvta.to.shared.u64 t, %1; cvt.u32.u64 %0, t; }" : "=r"(a) : "l"(p));
    return a;
}
#define LDMX4(r0, r1, r2, r3, a) \
    asm volatile("ldmatrix.sync.aligned.m8n8.x4.shared.b16 {%0,%1,%2,%3}, [%4];" \
                 : "=r"(r0), "=r"(r1), "=r"(r2), "=r"(r3) : "r"(a))
#define MMA(c, a0, a1, a2, a3, b0, b1) \
    asm volatile("mma.sync.aligned.m16n8k16.row.col.f32.bf16.bf16.f32 " \
                 "{%0,%1,%2,%3}, {%4,%5,%6,%7}, {%8,%9}, {%0,%1,%2,%3};" \
                 : "+f"((c)[0]), "+f"((c)[1]), "+f"((c)[2]), "+f"((c)[3]) \
                 : "r"(a0), "r"(a1), "r"(a2), "r"(a3), "r"(b0), "r"(b1))

__device__ __forceinline__ void split4(float4 v, uint2& hi, uint2& lo) {
    __nv_bfloat16 hx = __float2bfloat16(v.x), hy = __float2bfloat16(v.y);
    __nv_bfloat16 hz = __float2bfloat16(v.z), hw = __float2bfloat16(v.w);
    __nv_bfloat16 lx = __float2bfloat16(v.x - __bfloat162float(hx));
    __nv_bfloat16 ly = __float2bfloat16(v.y - __bfloat162float(hy));
    __nv_bfloat16 lz = __float2bfloat16(v.z - __bfloat162float(hz));
    __nv_bfloat16 lw = __float2bfloat16(v.w - __bfloat162float(hw));
    hi.x = ((uint32_t)__bfloat16_as_ushort(hy) << 16) | __bfloat16_as_ushort(hx);
    hi.y = ((uint32_t)__bfloat16_as_ushort(hw) << 16) | __bfloat16_as_ushort(hz);
    lo.x = ((uint32_t)__bfloat16_as_ushort(ly) << 16) | __bfloat16_as_ushort(lx);
    lo.y = ((uint32_t)__bfloat16_as_ushort(lw) << 16) | __bfloat16_as_ushort(lz);
}

// ---------------------------------------------------------------- CSR build
__global__ void zero_count_kernel(int N) {
    int i = blockIdx.x * blockDim.x + threadIdx.x;
    if (i == 0) g_is64 = 1;
    if (i < N) g_count[i] = 0;
}
__global__ void detect_kernel(const long long* __restrict__ ei, int nwords, int N) {
    int i = threadIdx.x + blockIdx.x * blockDim.x;
    if (i < nwords && (unsigned long long)ei[i] >= (unsigned long long)N)
        atomicAnd(&g_is64, 0);
}
// 1 edge/thread; index read as 32-bit low word for both dtypes (values < 2^31)
__global__ void hist_kernel(const void* __restrict__ ei_raw, int E, int N) {
    int e = blockIdx.x * blockDim.x + threadIdx.x;
    if (e >= E) return;
    const int* di = (const int*)ei_raw;
    int idx = g_is64 ? 2 * (E + e) : (E + e);
    int d = __ldg(&di[idx]);
    if ((unsigned)d < (unsigned)N) atomicAdd(&g_count[d], 1);
}
__global__ void scan1_kernel(int N) {
    __shared__ int s[SCANB];
    int i = blockIdx.x * SCANB + threadIdx.x;
    int v = (i < N) ? g_count[i] : 0;
    s[threadIdx.x] = v;
    __syncthreads();
    for (int off = 1; off < SCANB; off <<= 1) {
        int u = (threadIdx.x >= off) ? s[threadIdx.x - off] : 0;
        __syncthreads(); s[threadIdx.x] += u; __syncthreads();
    }
    if (threadIdx.x == SCANB - 1) g_bsum[blockIdx.x] = s[SCANB - 1];
}
__global__ void scan2_kernel(int nblk, int N) {
    __shared__ int s[SCANB];
    int t = threadIdx.x;
    int v = (t < nblk) ? g_bsum[t] : 0;
    s[t] = v; __syncthreads();
    for (int off = 1; off < SCANB; off <<= 1) {
        int u = (t >= off) ? s[t - off] : 0;
        __syncthreads(); s[t] += u; __syncthreads();
    }
    if (t < nblk) g_boff[t] = s[t] - v;
    if (t == SCANB - 1) g_off[N] = s[SCANB - 1];
}
__global__ void scan3_kernel(int N) {
    __shared__ int s[SCANB];
    int i = blockIdx.x * SCANB + threadIdx.x;
    int v = (i < N) ? g_count[i] : 0;
    s[threadIdx.x] = v; __syncthreads();
    for (int off = 1; off < SCANB; off <<= 1) {
        int u = (threadIdx.x >= off) ? s[threadIdx.x - off] : 0;
        __syncthreads(); s[threadIdx.x] += u; __syncthreads();
    }
    if (i < N) {
        int excl = g_boff[blockIdx.x] + s[threadIdx.x] - v;
        g_off[i] = excl;
        g_cursor[i] = excl;
    }
}
// 1 edge/thread; 32-bit low-word index reads
__global__ void scatter_kernel(const void* __restrict__ ei_raw, int E, int N) {
    int e = blockIdx.x * blockDim.x + threadIdx.x;
    if (e >= E) return;
    const int* di = (const int*)ei_raw;
    int s, d;
    if (g_is64) { s = __ldg(&di[2 * e]); d = __ldg(&di[2 * (E + e)]); }
    else        { s = __ldg(&di[e]);     d = __ldg(&di[E + e]); }
    if ((unsigned)s >= (unsigned)N || (unsigned)d >= (unsigned)N) return;
    int pos = atomicAdd(&g_cursor[d], 1);
    g_srcs[pos] = s;
}
// one warp per node, MLP=4
__global__ void gather_kernel(const float4* __restrict__ x, int N) {
    int w = (blockIdx.x * blockDim.x + threadIdx.x) >> 5;
    int lane = threadIdx.x & 31;
    if (w >= N) return;
    int beg = g_off[w], end = g_off[w + 1];
    float4 acc = make_float4(0.f, 0.f, 0.f, 0.f);
    for (int j = beg; j < end; j += 32) {
        int cnt = end - j; if (cnt > 32) cnt = 32;
        int s = (lane < cnt) ? g_srcs[j + lane] : 0;
        int i = 0;
        for (; i + 4 <= cnt; i += 4) {
            int s0 = __shfl_sync(0xffffffffu, s, i);
            int s1 = __shfl_sync(0xffffffffu, s, i + 1);
            int s2 = __shfl_sync(0xffffffffu, s, i + 2);
            int s3 = __shfl_sync(0xffffffffu, s, i + 3);
            float4 v0 = x[(size_t)s0 * 32 + lane];
            float4 v1 = x[(size_t)s1 * 32 + lane];
            float4 v2 = x[(size_t)s2 * 32 + lane];
            float4 v3 = x[(size_t)s3 * 32 + lane];
            acc.x += v0.x + v1.x + v2.x + v3.x;
            acc.y += v0.y + v1.y + v2.y + v3.y;
            acc.z += v0.z + v1.z + v2.z + v3.z;
            acc.w += v0.w + v1.w + v2.w + v3.w;
        }
        for (; i < cnt; i++) {
            int si = __shfl_sync(0xffffffffu, s, i);
            float4 v = x[(size_t)si * 32 + lane];
            acc.x += v.x; acc.y += v.y; acc.z += v.z; acc.w += v.w;
        }
    }
    ((float4*)g_agg)[(size_t)w * 32 + lane] = acc;
}

// ---------------------------------------------------------------- W pre-split
__global__ void wprep_kernel(const float* __restrict__ W_rel,
                             const float* __restrict__ W_root) {
    int q = blockIdx.x * blockDim.x + threadIdx.x;     // 8192 quads
    if (q >= DOUT * 256 / 4) return;
    int row = q >> 6;
    int k = (q & 63) * 4;
    int c = k >> 6, kk = k & 63;
    const float* src = (c < 2) ? &W_rel[row * DIN + c * KC + kk]
                               : &W_root[row * DIN + (c - 2) * KC + kk];
    float4 v = *(const float4*)src;
    uint2 h, l; split4(v, h, l);
    int didx = (c * 128 + row) * KC + kk;
    *(uint2*)((char*)g_Bh + didx * 2) = h;
    *(uint2*)((char*)g_Bl + didx * 2) = l;
}

// ---------------------------------------------------------------- HMMA GEMM
// smem: B chunk c hi at (2c)*TB, lo at (2c+1)*TB; A hi at 8*TB, lo at 9*TB
__global__ __launch_bounds__(256, 1)
void gemm_hmma_kernel(const float* __restrict__ x,
                      const float* __restrict__ bias,
                      float* __restrict__ out, int N) {
    extern __shared__ __nv_bfloat16 smem[];
    uint32_t base = smem_u32(smem);
    int tid = threadIdx.x, wid = tid >> 5, lane = tid & 31;
    int wm = wid & 3, wn = wid >> 2;
    int node0 = blockIdx.x * MTILE;

    // ---- B: all 4 chunks hi/lo via cp.async from pre-split globals
    #pragma unroll
    for (int i = 0; i < 32; i++) {
        int o = tid + i * 256;                  // [0,8192) 16B segments
        int c = o >> 11;
        int hl = (o >> 10) & 1;
        int row = (o >> 3) & 127;
        int seg = o & 7;
        const __nv_bfloat16* g = (hl ? g_Bl : g_Bh) + ((c * 128 + row) * KC + seg * 8);
        uint32_t dst = base + (uint32_t)(c * 2 + hl) * TB + row * (PITCH * 2) + seg * 16;
        asm volatile("cp.async.cg.shared.global [%0], [%1], 16;" :: "r"(dst), "l"(g));
    }
    asm volatile("cp.async.commit_group;" ::: "memory");

    float acc[2][8][4];
    #pragma unroll
    for (int a = 0; a < 2; a++)
        #pragma unroll
        for (int b = 0; b < 8; b++)
            #pragma unroll
            for (int c = 0; c < 4; c++) acc[a][b][c] = 0.f;

    uint32_t aoff = (uint32_t)((wm * 32 + (lane & 15)) * PITCH + (lane >> 4) * 8) * 2;
    uint32_t brow = (uint32_t)(wn * 64 + (lane & 7) + ((lane >> 4) << 3));
    uint32_t boff = (uint32_t)(brow * PITCH + ((lane >> 3) & 1) * 8) * 2;

    __nv_bfloat16* sAh = smem + 8 * T_ELEMS;
    __nv_bfloat16* sAl = smem + 9 * T_ELEMS;
    uint32_t Ab = base + 8u * TB;

    for (int c = 0; c < NCHUNK; c++) {
        // ---- A chunk: load f32, split, STS (register-neutral)
        const float* asrc = (c < 2) ? g_agg + (size_t)node0 * DIN + c * KC
                                    : x + (size_t)node0 * DIN + (c - 2) * KC;
        #pragma unroll
        for (int i = 0; i < 8; i++) {
            int idx = tid + i * 256;
            int row = idx >> 4, c4 = idx & 15;
            float4 v = make_float4(0.f, 0.f, 0.f, 0.f);
            if (node0 + row < N) v = ((const float4*)(asrc + (size_t)row * DIN))[c4];
            uint2 h, l; split4(v, h, l);
            *(uint2*)((char*)sAh + row * (PITCH * 2) + c4 * 8) = h;
            *(uint2*)((char*)sAl + row * (PITCH * 2) + c4 * 8) = l;
        }
        if (c == 0) asm volatile("cp.async.wait_group 0;" ::: "memory");
        __syncthreads();

        uint32_t Bb = base + (uint32_t)(c * 2) * TB;
        #pragma unroll
        for (int kt = 0; kt < 4; kt++) {
            uint32_t kb = kt * 32;
            uint32_t Ah[8], Al[8], Bh[16], Bl[16];
            #pragma unroll
            for (int tm = 0; tm < 2; tm++) {
                uint32_t a = Ab + aoff + (uint32_t)(tm * 16 * PITCH) * 2 + kb;
                LDMX4(Ah[tm*4+0], Ah[tm*4+1], Ah[tm*4+2], Ah[tm*4+3], a);
                LDMX4(Al[tm*4+0], Al[tm*4+1], Al[tm*4+2], Al[tm*4+3], a + TB);
            }
            #pragma unroll
            for (int p = 0; p < 4; p++) {
                uint32_t bb2 = Bb + boff + (uint32_t)(p * 16 * PITCH) * 2 + kb;
                LDMX4(Bh[p*4+0], Bh[p*4+1], Bh[p*4+2], Bh[p*4+3], bb2);
                LDMX4(Bl[p*4+0], Bl[p*4+1], Bl[p*4+2], Bl[p*4+3], bb2 + TB);
            }
            #pragma unroll
            for (int tm = 0; tm < 2; tm++)
                #pragma unroll
                for (int tn = 0; tn < 8; tn++) {
                    int bi = (tn >> 1) * 4 + (tn & 1) * 2;
                    MMA(acc[tm][tn], Ah[tm*4+0], Ah[tm*4+1], Ah[tm*4+2], Ah[tm*4+3],
                        Bh[bi], Bh[bi+1]);
                    MMA(acc[tm][tn], Al[tm*4+0], Al[tm*4+1], Al[tm*4+2], Al[tm*4+3],
                        Bh[bi], Bh[bi+1]);
                    MMA(acc[tm][tn], Ah[tm*4+0], Ah[tm*4+1], Ah[tm*4+2], Ah[tm*4+3],
                        Bl[bi], Bl[bi+1]);
                }
        }
        __syncthreads();
    }

    // ---- epilogue: bias + relu, float2 stores
    #pragma unroll
    for (int tn = 0; tn < 8; tn++) {
        int col = wn * 64 + tn * 8 + 2 * (lane & 3);
        float2 bb = *(const float2*)&bias[col];
        #pragma unroll
        for (int tm = 0; tm < 2; tm++) {
            int row = node0 + wm * 32 + tm * 16 + (lane >> 2);
            if (row < N) {
                float2 v0;
                v0.x = fmaxf(acc[tm][tn][0] + bb.x, 0.f);
                v0.y = fmaxf(acc[tm][tn][1] + bb.y, 0.f);
                *(float2*)(out + (size_t)row * DOUT + col) = v0;
            }
            if (row + 8 < N) {
                float2 v1;
                v1.x = fmaxf(acc[tm][tn][2] + bb.x, 0.f);
                v1.y = fmaxf(acc[tm][tn][3] + bb.y, 0.f);
                *(float2*)(out + (size_t)(row + 8) * DOUT + col) = v1;
            }
        }
    }
}

// ---------------------------------------------------------------- launch
extern "C" void kernel_launch(void* const* d_in, const int* in_sizes, int n_in,
                              void* d_out, int out_size) {
    const float* x      = (const float*)d_in[0];
    const void*  ei     = d_in[1];
    const float* W_rel  = (const float*)d_in[2];
    const float* b_rel  = (const float*)d_in[3];
    const float* W_root = (const float*)d_in[4];
    float* out = (float*)d_out;

    int N = in_sizes[0] / DIN;     // 50000
    int E = in_sizes[1] / 2;       // 800000
    int nblk = (N + SCANB - 1) / SCANB;

    zero_count_kernel<<<(N + 255) / 256, 256>>>(N);
    detect_kernel<<<4, 256>>>((const long long*)ei, 1024, N);
    wprep_kernel<<<(DOUT * 256 / 4 + 255) / 256, 256>>>(W_rel, W_root);
    hist_kernel<<<(E + 255) / 256, 256>>>(ei, E, N);
    scan1_kernel<<<nblk, SCANB>>>(N);
    scan2_kernel<<<1, SCANB>>>(nblk, N);
    scan3_kernel<<<nblk, SCANB>>>(N);
    scatter_kernel<<<(E + 255) / 256, 256>>>(ei, E, N);
    gather_kernel<<<(N * 32 + 255) / 256, 256>>>((const float4*)x, N);

    cudaFuncSetAttribute(gemm_hmma_kernel,
                         cudaFuncAttributeMaxDynamicSharedMemorySize, SMEM_TOTAL);
    gemm_hmma_kernel<<<(N + MTILE - 1) / MTILE, 256, SMEM_TOTAL>>>(x, b_rel, out, N);
}

// round 12
// speedup vs baseline: 1.3859x; 1.0393x over previous
#include <cuda_runtime.h>
#include <cuda_bf16.h>
#include <cstdint>

#define DIN   128
#define DOUT  128
#define MTILE 128
#define KC    64
#define NCHUNK 4
#define MAXN  50000
#define MAXE  800000
#define PITCH 72                    // bf16 per smem row (conflict-free ldmatrix)
#define T_ELEMS (128 * PITCH)
#define TB (T_ELEMS * 2)            // 18432 bytes per tile
// smem: A hi/lo (tiles 0,1) + B double-buffer (tiles 2..5) = 6 tiles
#define SMEM_TOTAL (6 * TB)         // 110592 -> 2 CTAs/SM

#define SCANB 256
#define NBLK ((MAXN + SCANB - 1) / SCANB)

__device__ float g_agg[MAXN * DIN];
__device__ int   g_count[MAXN];
__device__ int   g_off[MAXN + 1];
__device__ int   g_cursor[MAXN];
__device__ int   g_srcs[MAXE];
__device__ int   g_bsum[NBLK];
__device__ int   g_boff[NBLK];
__device__ __nv_bfloat16 g_Bh[NCHUNK * 128 * KC];
__device__ __nv_bfloat16 g_Bl[NCHUNK * 128 * KC];
__device__ int   g_is64;

// ---------------------------------------------------------------- helpers
__device__ __forceinline__ uint32_t smem_u32(const void* p) {
    uint32_t a;
    asm("{ .reg .u64 t; cvta.to.shared.u64 t, %1; cvt.u32.u64 %0, t; }" : "=r"(a) : "l"(p));
    return a;
}
#define LDMX4(r0, r1, r2, r3, a) \
    asm volatile("ldmatrix.sync.aligned.m8n8.x4.shared.b16 {%0,%1,%2,%3}, [%4];" \
                 : "=r"(r0), "=r"(r1), "=r"(r2), "=r"(r3) : "r"(a))
#define MMA(c, a0, a1, a2, a3, b0, b1) \
    asm volatile("mma.sync.aligned.m16n8k16.row.col.f32.bf16.bf16.f32 " \
                 "{%0,%1,%2,%3}, {%4,%5,%6,%7}, {%8,%9}, {%0,%1,%2,%3};" \
                 : "+f"((c)[0]), "+f"((c)[1]), "+f"((c)[2]), "+f"((c)[3]) \
                 : "r"(a0), "r"(a1), "r"(a2), "r"(a3), "r"(b0), "r"(b1))

__device__ __forceinline__ void split4(float4 v, uint2& hi, uint2& lo) {
    __nv_bfloat16 hx = __float2bfloat16(v.x), hy = __float2bfloat16(v.y);
    __nv_bfloat16 hz = __float2bfloat16(v.z), hw = __float2bfloat16(v.w);
    __nv_bfloat16 lx = __float2bfloat16(v.x - __bfloat162float(hx));
    __nv_bfloat16 ly = __float2bfloat16(v.y - __bfloat162float(hy));
    __nv_bfloat16 lz = __float2bfloat16(v.z - __bfloat162float(hz));
    __nv_bfloat16 lw = __float2bfloat16(v.w - __bfloat162float(hw));
    hi.x = ((uint32_t)__bfloat16_as_ushort(hy) << 16) | __bfloat16_as_ushort(hx);
    hi.y = ((uint32_t)__bfloat16_as_ushort(hw) << 16) | __bfloat16_as_ushort(hz);
    lo.x = ((uint32_t)__bfloat16_as_ushort(ly) << 16) | __bfloat16_as_ushort(lx);
    lo.y = ((uint32_t)__bfloat16_as_ushort(lw) << 16) | __bfloat16_as_ushort(lz);
}

// ---------------------------------------------------------------- CSR build
__global__ void zero_count_kernel(int N) {
    int i = blockIdx.x * blockDim.x + threadIdx.x;
    if (i == 0) g_is64 = 1;
    if (i < N) g_count[i] = 0;
}
__global__ void detect_kernel(const long long* __restrict__ ei, int nwords, int N) {
    int i = threadIdx.x + blockIdx.x * blockDim.x;
    if (i < nwords && (unsigned long long)ei[i] >= (unsigned long long)N)
        atomicAnd(&g_is64, 0);
}
__global__ void hist_kernel(const void* __restrict__ ei_raw, int E, int N) {
    int e = blockIdx.x * blockDim.x + threadIdx.x;
    if (e >= E) return;
    const int* di = (const int*)ei_raw;
    int idx = g_is64 ? 2 * (E + e) : (E + e);
    int d = __ldg(&di[idx]);
    if ((unsigned)d < (unsigned)N) atomicAdd(&g_count[d], 1);
}
__global__ void scan1_kernel(int N) {
    __shared__ int s[SCANB];
    int i = blockIdx.x * SCANB + threadIdx.x;
    int v = (i < N) ? g_count[i] : 0;
    s[threadIdx.x] = v;
    __syncthreads();
    for (int off = 1; off < SCANB; off <<= 1) {
        int u = (threadIdx.x >= off) ? s[threadIdx.x - off] : 0;
        __syncthreads(); s[threadIdx.x] += u; __syncthreads();
    }
    if (threadIdx.x == SCANB - 1) g_bsum[blockIdx.x] = s[SCANB - 1];
}
__global__ void scan2_kernel(int nblk, int N) {
    __shared__ int s[SCANB];
    int t = threadIdx.x;
    int v = (t < nblk) ? g_bsum[t] : 0;
    s[t] = v; __syncthreads();
    for (int off = 1; off < SCANB; off <<= 1) {
        int u = (t >= off) ? s[t - off] : 0;
        __syncthreads(); s[t] += u; __syncthreads();
    }
    if (t < nblk) g_boff[t] = s[t] - v;
    if (t == SCANB - 1) g_off[N] = s[SCANB - 1];
}
__global__ void scan3_kernel(int N) {
    __shared__ int s[SCANB];
    int i = blockIdx.x * SCANB + threadIdx.x;
    int v = (i < N) ? g_count[i] : 0;
    s[threadIdx.x] = v; __syncthreads();
    for (int off = 1; off < SCANB; off <<= 1) {
        int u = (threadIdx.x >= off) ? s[threadIdx.x - off] : 0;
        __syncthreads(); s[threadIdx.x] += u; __syncthreads();
    }
    if (i < N) {
        int excl = g_boff[blockIdx.x] + s[threadIdx.x] - v;
        g_off[i] = excl;
        g_cursor[i] = excl;
    }
}
__global__ void scatter_kernel(const void* __restrict__ ei_raw, int E, int N) {
    int e = blockIdx.x * blockDim.x + threadIdx.x;
    if (e >= E) return;
    const int* di = (const int*)ei_raw;
    int s, d;
    if (g_is64) { s = __ldg(&di[2 * e]); d = __ldg(&di[2 * (E + e)]); }
    else        { s = __ldg(&di[e]);     d = __ldg(&di[E + e]); }
    if ((unsigned)s >= (unsigned)N || (unsigned)d >= (unsigned)N) return;
    int pos = atomicAdd(&g_cursor[d], 1);
    g_srcs[pos] = s;
}
__global__ void gather_kernel(const float4* __restrict__ x, int N) {
    int w = (blockIdx.x * blockDim.x + threadIdx.x) >> 5;
    int lane = threadIdx.x & 31;
    if (w >= N) return;
    int beg = g_off[w], end = g_off[w + 1];
    float4 acc = make_float4(0.f, 0.f, 0.f, 0.f);
    for (int j = beg; j < end; j += 32) {
        int cnt = end - j; if (cnt > 32) cnt = 32;
        int s = (lane < cnt) ? g_srcs[j + lane] : 0;
        int i = 0;
        for (; i + 4 <= cnt; i += 4) {
            int s0 = __shfl_sync(0xffffffffu, s, i);
            int s1 = __shfl_sync(0xffffffffu, s, i + 1);
            int s2 = __shfl_sync(0xffffffffu, s, i + 2);
            int s3 = __shfl_sync(0xffffffffu, s, i + 3);
            float4 v0 = x[(size_t)s0 * 32 + lane];
            float4 v1 = x[(size_t)s1 * 32 + lane];
            float4 v2 = x[(size_t)s2 * 32 + lane];
            float4 v3 = x[(size_t)s3 * 32 + lane];
            acc.x += v0.x + v1.x + v2.x + v3.x;
            acc.y += v0.y + v1.y + v2.y + v3.y;
            acc.z += v0.z + v1.z + v2.z + v3.z;
            acc.w += v0.w + v1.w + v2.w + v3.w;
        }
        for (; i < cnt; i++) {
            int si = __shfl_sync(0xffffffffu, s, i);
            float4 v = x[(size_t)si * 32 + lane];
            acc.x += v.x; acc.y += v.y; acc.z += v.z; acc.w += v.w;
        }
    }
    ((float4*)g_agg)[(size_t)w * 32 + lane] = acc;
}

// ---------------------------------------------------------------- W pre-split
__global__ void wprep_kernel(const float* __restrict__ W_rel,
                             const float* __restrict__ W_root) {
    int q = blockIdx.x * blockDim.x + threadIdx.x;
    if (q >= DOUT * 256 / 4) return;
    int row = q >> 6;
    int k = (q & 63) * 4;
    int c = k >> 6, kk = k & 63;
    const float* src = (c < 2) ? &W_rel[row * DIN + c * KC + kk]
                               : &W_root[row * DIN + (c - 2) * KC + kk];
    float4 v = *(const float4*)src;
    uint2 h, l; split4(v, h, l);
    int didx = (c * 128 + row) * KC + kk;
    *(uint2*)((char*)g_Bh + didx * 2) = h;
    *(uint2*)((char*)g_Bl + didx * 2) = l;
}

// ---------------------------------------------------------------- HMMA GEMM
// 2 CTAs/SM: A hi/lo tiles 0,1; B double-buffer buf b: hi tile (2+2b), lo (3+2b)
__global__ __launch_bounds__(256, 2)
void gemm_hmma_kernel(const float* __restrict__ x,
                      const float* __restrict__ bias,
                      float* __restrict__ out, int N) {
    extern __shared__ __nv_bfloat16 smem[];
    uint32_t base = smem_u32(smem);
    int tid = threadIdx.x, wid = tid >> 5, lane = tid & 31;
    int wm = wid & 3, wn = wid >> 2;
    int node0 = blockIdx.x * MTILE;

    // ---- prologue: B chunk 0 -> buf 0 via cp.async
    {
        #pragma unroll
        for (int i = 0; i < 8; i++) {
            int o = tid + i * 256;              // [0,2048) 16B segments
            int hl = o >> 10;
            int row = (o >> 3) & 127;
            int seg = o & 7;
            const __nv_bfloat16* g = (hl ? g_Bl : g_Bh) + ((0 * 128 + row) * KC + seg * 8);
            uint32_t dst = base + (uint32_t)(2 + hl) * TB + row * (PITCH * 2) + seg * 16;
            asm volatile("cp.async.cg.shared.global [%0], [%1], 16;" :: "r"(dst), "l"(g));
        }
        asm volatile("cp.async.commit_group;" ::: "memory");
    }

    float acc[2][8][4];
    #pragma unroll
    for (int a = 0; a < 2; a++)
        #pragma unroll
        for (int b = 0; b < 8; b++)
            #pragma unroll
            for (int c = 0; c < 4; c++) acc[a][b][c] = 0.f;

    uint32_t aoff = (uint32_t)((wm * 32 + (lane & 15)) * PITCH + (lane >> 4) * 8) * 2;
    uint32_t brow = (uint32_t)(wn * 64 + (lane & 7) + ((lane >> 4) << 3));
    uint32_t boff = (uint32_t)(brow * PITCH + ((lane >> 3) & 1) * 8) * 2;

    __nv_bfloat16* sAh = smem;
    __nv_bfloat16* sAl = smem + T_ELEMS;

    for (int c = 0; c < NCHUNK; c++) {
        int buf = c & 1;
        // prefetch B chunk c+1 into the other buffer
        if (c + 1 < NCHUNK) {
            int cn = c + 1, bn = cn & 1;
            #pragma unroll
            for (int i = 0; i < 8; i++) {
                int o = tid + i * 256;
                int hl = o >> 10;
                int row = (o >> 3) & 127;
                int seg = o & 7;
                const __nv_bfloat16* g = (hl ? g_Bl : g_Bh) + ((cn * 128 + row) * KC + seg * 8);
                uint32_t dst = base + (uint32_t)(2 + 2 * bn + hl) * TB + row * (PITCH * 2) + seg * 16;
                asm volatile("cp.async.cg.shared.global [%0], [%1], 16;" :: "r"(dst), "l"(g));
            }
            asm volatile("cp.async.commit_group;" ::: "memory");
        }

        // ---- A chunk: load f32, split, STS
        const float* asrc = (c < 2) ? g_agg + (size_t)node0 * DIN + c * KC
                                    : x + (size_t)node0 * DIN + (c - 2) * KC;
        #pragma unroll
        for (int i = 0; i < 8; i++) {
            int idx = tid + i * 256;
            int row = idx >> 4, c4 = idx & 15;
            float4 v = make_float4(0.f, 0.f, 0.f, 0.f);
            if (node0 + row < N) v = ((const float4*)(asrc + (size_t)row * DIN))[c4];
            uint2 h, l; split4(v, h, l);
            *(uint2*)((char*)sAh + row * (PITCH * 2) + c4 * 8) = h;
            *(uint2*)((char*)sAl + row * (PITCH * 2) + c4 * 8) = l;
        }
        if (c + 1 < NCHUNK)
            asm volatile("cp.async.wait_group 1;" ::: "memory");   // B_c ready
        else
            asm volatile("cp.async.wait_group 0;" ::: "memory");
        __syncthreads();

        uint32_t Ab = base;
        uint32_t Bb = base + (uint32_t)(2 + 2 * buf) * TB;
        #pragma unroll
        for (int kt = 0; kt < 4; kt++) {
            uint32_t kb = kt * 32;
            uint32_t Ah[8], Al[8];
            #pragma unroll
            for (int tm = 0; tm < 2; tm++) {
                uint32_t a = Ab + aoff + (uint32_t)(tm * 16 * PITCH) * 2 + kb;
                LDMX4(Ah[tm*4+0], Ah[tm*4+1], Ah[tm*4+2], Ah[tm*4+3], a);
                LDMX4(Al[tm*4+0], Al[tm*4+1], Al[tm*4+2], Al[tm*4+3], a + TB);
            }
            // two tn-halves: only half the B fragments live at a time
            #pragma unroll
            for (int h = 0; h < 2; h++) {
                uint32_t Bh[8], Bl[8];
                #pragma unroll
                for (int pp = 0; pp < 2; pp++) {
                    int p = h * 2 + pp;
                    uint32_t bb2 = Bb + boff + (uint32_t)(p * 16 * PITCH) * 2 + kb;
                    LDMX4(Bh[pp*4+0], Bh[pp*4+1], Bh[pp*4+2], Bh[pp*4+3], bb2);
                    LDMX4(Bl[pp*4+0], Bl[pp*4+1], Bl[pp*4+2], Bl[pp*4+3], bb2 + TB);
                }
                #pragma unroll
                for (int tm = 0; tm < 2; tm++)
                    #pragma unroll
                    for (int tnl = 0; tnl < 4; tnl++) {
                        int tn = h * 4 + tnl;
                        int bi = (tnl >> 1) * 4 + (tnl & 1) * 2;
                        MMA(acc[tm][tn], Ah[tm*4+0], Ah[tm*4+1], Ah[tm*4+2], Ah[tm*4+3],
                            Bh[bi], Bh[bi+1]);
                        MMA(acc[tm][tn], Al[tm*4+0], Al[tm*4+1], Al[tm*4+2], Al[tm*4+3],
                            Bh[bi], Bh[bi+1]);
                        MMA(acc[tm][tn], Ah[tm*4+0], Ah[tm*4+1], Ah[tm*4+2], Ah[tm*4+3],
                            Bl[bi], Bl[bi+1]);
                    }
            }
        }
        __syncthreads();
    }

    // ---- epilogue: bias + relu, float2 stores
    #pragma unroll
    for (int tn = 0; tn < 8; tn++) {
        int col = wn * 64 + tn * 8 + 2 * (lane & 3);
        float2 bb = *(const float2*)&bias[col];
        #pragma unroll
        for (int tm = 0; tm < 2; tm++) {
            int row = node0 + wm * 32 + tm * 16 + (lane >> 2);
            if (row < N) {
                float2 v0;
                v0.x = fmaxf(acc[tm][tn][0] + bb.x, 0.f);
                v0.y = fmaxf(acc[tm][tn][1] + bb.y, 0.f);
                *(float2*)(out + (size_t)row * DOUT + col) = v0;
            }
            if (row + 8 < N) {
                float2 v1;
                v1.x = fmaxf(acc[tm][tn][2] + bb.x, 0.f);
                v1.y = fmaxf(acc[tm][tn][3] + bb.y, 0.f);
                *(float2*)(out + (size_t)(row + 8) * DOUT + col) = v1;
            }
        }
    }
}

// ---------------------------------------------------------------- launch
extern "C" void kernel_launch(void* const* d_in, const int* in_sizes, int n_in,
                              void* d_out, int out_size) {
    const float* x      = (const float*)d_in[0];
    const void*  ei     = d_in[1];
    const float* W_rel  = (const float*)d_in[2];
    const float* b_rel  = (const float*)d_in[3];
    const float* W_root = (const float*)d_in[4];
    float* out = (float*)d_out;

    int N = in_sizes[0] / DIN;     // 50000
    int E = in_sizes[1] / 2;       // 800000
    int nblk = (N + SCANB - 1) / SCANB;

    zero_count_kernel<<<(N + 255) / 256, 256>>>(N);
    detect_kernel<<<4, 256>>>((const long long*)ei, 1024, N);
    wprep_kernel<<<(DOUT * 256 / 4 + 255) / 256, 256>>>(W_rel, W_root);
    hist_kernel<<<(E + 255) / 256, 256>>>(ei, E, N);
    scan1_kernel<<<nblk, SCANB>>>(N);
    scan2_kernel<<<1, SCANB>>>(nblk, N);
    scan3_kernel<<<nblk, SCANB>>>(N);
    scatter_kernel<<<(E + 255) / 256, 256>>>(ei, E, N);
    gather_kernel<<<(N * 32 + 255) / 256, 256>>>((const float4*)x, N);

    cudaFuncSetAttribute(gemm_hmma_kernel,
                         cudaFuncAttributeMaxDynamicSharedMemorySize, SMEM_TOTAL);
    gemm_hmma_kernel<<<(N + MTILE - 1) / MTILE, 256, SMEM_TOTAL>>>(x, b_rel, out, N);
}